// round 1
// baseline (speedup 1.0000x reference)
#include <cuda_runtime.h>
#include <math.h>

#define Hh    256
#define Bb    64
#define Ss    512
#define DIN   2818
#define DTXT  512
#define M1    32768   // Bb*Ss

// ---------------- scratch (device globals; no allocation allowed) ----------------
__device__ float    g_xfeat[(size_t)M1 * Hh];          // [s*64+b][h]   33.5 MB
__device__ float    g_xg[2][4 * Hh][M1];               // [dir][gate][s*64+b]  268 MB
__device__ float    g_hbuf[2][2][Bb][Hh];              // [parity][dir][b][h]
__device__ float    g_gate[Bb * Hh];                   // [b][h]
__device__ float    g_vfeat[Bb][2 * Hh];               // [b][2H]
__device__ unsigned g_bar[2];

__device__ __forceinline__ float fsig(float x)  { return 1.f / (1.f + __expf(-x)); }
__device__ __forceinline__ float ftanh_(float x){ return 2.f / (1.f + __expf(-2.f * x)) - 1.f; }

__device__ __forceinline__ unsigned ldacq(const unsigned* p) {
    unsigned v;
    asm volatile("ld.global.acquire.gpu.u32 %0, [%1];" : "=r"(v) : "l"(p));
    return v;
}

// ---------------- text gate: gate[b][h] = sigmoid(W2 relu(W1 t + b1) + b2) ----------------
__global__ void gate_kernel(const float* __restrict__ txt,
                            const float* __restrict__ Wg1, const float* __restrict__ bg1,
                            const float* __restrict__ Wg2, const float* __restrict__ bg2)
{
    __shared__ float ts[DTXT];
    __shared__ float hs[Hh];
    int b = blockIdx.x, tid = threadIdx.x;
    for (int i = tid; i < DTXT; i += 256) ts[i] = txt[b * DTXT + i];
    __syncthreads();
    float s = bg1[tid];
    const float4* wr = (const float4*)(Wg1 + (size_t)tid * DTXT);
    const float4* tv = (const float4*)ts;
#pragma unroll 8
    for (int i = 0; i < DTXT / 4; i++) {
        float4 w = wr[i], t = tv[i];
        s += w.x * t.x + w.y * t.y + w.z * t.z + w.w * t.w;
    }
    hs[tid] = fmaxf(s, 0.f);
    __syncthreads();
    float s2 = bg2[tid];
    const float4* wr2 = (const float4*)(Wg2 + (size_t)tid * Hh);
    const float4* hv  = (const float4*)hs;
#pragma unroll 8
    for (int i = 0; i < Hh / 4; i++) {
        float4 w = wr2[i], t = hv[i];
        s2 += w.x * t.x + w.y * t.y + w.z * t.z + w.w * t.w;
    }
    g_gate[b * Hh + tid] = fsig(s2);
}

// ---------------- GEMM1: x_feat[(s*64+b)][h] = (x[b,s,:]·Wvp[h,:] + bvp[h]) * gate[b][h] ----------------
__global__ __launch_bounds__(256) void gemm1_kernel(const float* __restrict__ A,
                                                    const float* __restrict__ Wvp,
                                                    const float* __restrict__ bvp)
{
    __shared__ float As[8][132];
    __shared__ float Bs[8][132];
    int tid = threadIdx.x;
    int m0 = blockIdx.x * 128, n0 = blockIdx.y * 128;
    int tx = tid & 15, ty = tid >> 4;
    float acc[8][8];
#pragma unroll
    for (int i = 0; i < 8; i++)
#pragma unroll
        for (int j = 0; j < 8; j++) acc[i][j] = 0.f;

    for (int kt = 0; kt < DIN; kt += 8) {
#pragma unroll
        for (int i = 0; i < 2; i++) {
            int lin = tid + i * 256;
            int row = lin >> 2;
            int kp  = (lin & 3) << 1;
            int k   = kt + kp;
            float2 va = make_float2(0.f, 0.f), vb = make_float2(0.f, 0.f);
            if (k + 1 < DIN) {
                va = *(const float2*)(A   + (size_t)(m0 + row) * DIN + k);
                vb = *(const float2*)(Wvp + (size_t)(n0 + row) * DIN + k);
            } else if (k < DIN) {
                va.x = A  [(size_t)(m0 + row) * DIN + k];
                vb.x = Wvp[(size_t)(n0 + row) * DIN + k];
            }
            As[kp][row] = va.x; As[kp + 1][row] = va.y;
            Bs[kp][row] = vb.x; Bs[kp + 1][row] = vb.y;
        }
        __syncthreads();
#pragma unroll
        for (int k = 0; k < 8; k++) {
            float a[8], bv[8];
            *(float4*)&a[0]  = *(const float4*)&As[k][tx * 8];
            *(float4*)&a[4]  = *(const float4*)&As[k][tx * 8 + 4];
            *(float4*)&bv[0] = *(const float4*)&Bs[k][ty * 8];
            *(float4*)&bv[4] = *(const float4*)&Bs[k][ty * 8 + 4];
#pragma unroll
            for (int i = 0; i < 8; i++)
#pragma unroll
                for (int j = 0; j < 8; j++) acc[i][j] = fmaf(a[i], bv[j], acc[i][j]);
        }
        __syncthreads();
    }
    int bat = m0 >> 9;          // batch (m tiles never straddle a batch: 512 % 128 == 0)
    int sbase = m0 & 511;
#pragma unroll
    for (int i = 0; i < 8; i++) {
        int srow = sbase + tx * 8 + i;
        float* dst = g_xfeat + (size_t)(srow * Bb + bat) * Hh + n0 + ty * 8;
        float o[8];
#pragma unroll
        for (int j = 0; j < 8; j++) {
            int n = n0 + ty * 8 + j;
            o[j] = (acc[i][j] + bvp[n]) * g_gate[bat * Hh + n];
        }
        *(float4*)dst       = make_float4(o[0], o[1], o[2], o[3]);
        *(float4*)(dst + 4) = make_float4(o[4], o[5], o[6], o[7]);
    }
}

// ---------------- GEMM2: xg[dir][gate][m'] = x_feat[m']·Wih[gate] + bih+bhh ----------------
__global__ __launch_bounds__(256) void gemm2_kernel(const float* __restrict__ Wihf,
                                                    const float* __restrict__ Wihb,
                                                    const float* __restrict__ bihf, const float* __restrict__ bhhf,
                                                    const float* __restrict__ bihb, const float* __restrict__ bhhb)
{
    __shared__ float As[8][132];
    __shared__ float Bs[8][132];
    int tid = threadIdx.x;
    int m0  = blockIdx.x * 128;
    int n0g = blockIdx.y * 128;
    int dir = n0g >> 10;
    int n0  = n0g & 1023;
    const float* Wsrc = dir ? Wihb : Wihf;
    const float* bi   = dir ? bihb : bihf;
    const float* bh   = dir ? bhhb : bhhf;
    int tx = tid & 15, ty = tid >> 4;
    float acc[8][8];
#pragma unroll
    for (int i = 0; i < 8; i++)
#pragma unroll
        for (int j = 0; j < 8; j++) acc[i][j] = 0.f;

    for (int kt = 0; kt < Hh; kt += 8) {
#pragma unroll
        for (int i = 0; i < 2; i++) {
            int lin = tid + i * 256;
            int row = lin >> 2;
            int kp  = (lin & 3) << 1;
            int k   = kt + kp;
            float2 va = *(const float2*)(g_xfeat + (size_t)(m0 + row) * Hh + k);
            float2 vb = *(const float2*)(Wsrc    + (size_t)(n0 + row) * Hh + k);
            As[kp][row] = va.x; As[kp + 1][row] = va.y;
            Bs[kp][row] = vb.x; Bs[kp + 1][row] = vb.y;
        }
        __syncthreads();
#pragma unroll
        for (int k = 0; k < 8; k++) {
            float a[8], bv[8];
            *(float4*)&a[0]  = *(const float4*)&As[k][tx * 8];
            *(float4*)&a[4]  = *(const float4*)&As[k][tx * 8 + 4];
            *(float4*)&bv[0] = *(const float4*)&Bs[k][ty * 8];
            *(float4*)&bv[4] = *(const float4*)&Bs[k][ty * 8 + 4];
#pragma unroll
            for (int i = 0; i < 8; i++)
#pragma unroll
                for (int j = 0; j < 8; j++) acc[i][j] = fmaf(a[i], bv[j], acc[i][j]);
        }
        __syncthreads();
    }
#pragma unroll
    for (int j = 0; j < 8; j++) {
        int gr = n0 + ty * 8 + j;
        float bias = bi[gr] + bh[gr];
        float* dst = &g_xg[dir][gr][m0 + tx * 8];
        float o[8];
#pragma unroll
        for (int i = 0; i < 8; i++) o[i] = acc[i][j] + bias;
        *(float4*)dst       = make_float4(o[0], o[1], o[2], o[3]);
        *(float4*)(dst + 4) = make_float4(o[4], o[5], o[6], o[7]);
    }
}

// ---------------- barrier init ----------------
__global__ void init_kernel() {
    if (threadIdx.x < 2) g_bar[threadIdx.x] = 0u;
}

// ---------------- persistent bidirectional LSTM scan ----------------
// 128 CTAs: dir = blockIdx.x>>6, group c = blockIdx.x&63 owns h-dims [4c,4c+4) (16 gate rows).
// Per step: stage B computes the 16 gate pre-activations for all 64 batches from the
// CTA-resident Whh slice (SMEM) x full h (SMEM); stage C applies the LSTM cell for its
// 4 h-dims x 64 batches (c-state + running max in registers), publishes h through L2
// (parity double buffer), per-direction grid barrier, reload h.
#define SCAN_SMEM_BYTES ((64 * 256 + 16 * 260 + 16 * 68) * 4)

__global__ __launch_bounds__(256, 1) void scan_kernel(const float* __restrict__ Whhf,
                                                      const float* __restrict__ Whhb)
{
    extern __shared__ float sm[];
    float* hsm = sm;                    // [64][256]
    float* Wsm = sm + 64 * 256;         // [16][260]
    float* gsm = Wsm + 16 * 260;        // [16][68]

    int tid = threadIdx.x;
    int d = blockIdx.x >> 6;
    int c = blockIdx.x & 63;
    const float* Whh = d ? Whhb : Whhf;

    for (int idx = tid; idx < 16 * 256; idx += 256) {
        int r = idx >> 8, k = idx & 255;
        int q = r >> 2, j2 = r & 3;
        Wsm[r * 260 + k] = Whh[(size_t)(q * 256 + 4 * c + j2) * Hh + k];
    }
    for (int idx = tid; idx < 64 * 256; idx += 256) hsm[idx] = 0.f;

    int r  = tid & 15, bc = tid >> 4, b0 = bc << 2;
    int qr = r >> 2,  jr = r & 3;
    const float* xg_row = g_xg[d][qr * 256 + 4 * c + jr];
    const float* wr = &Wsm[r * 260];

    int jj = tid >> 6, b = tid & 63;    // stage-C identity (stable across steps)
    int jglob = 4 * c + jj;
    float cst = 0.f, vmax = -3.4e38f;

    __syncthreads();

    for (int step = 0; step < 512; step++) {
        int t = d ? (511 - step) : step;
        // ---- stage B: gates = xg + Whh·h ----
        float4 xa = *(const float4*)&xg_row[t * 64 + b0];
        float a0 = xa.x, a1 = xa.y, a2 = xa.z, a3 = xa.w;
        const float* h0 = &hsm[(size_t)b0 * 256];
        const float* h1 = h0 + 256;
        const float* h2 = h0 + 512;
        const float* h3 = h0 + 768;
#pragma unroll 8
        for (int k = 0; k < 256; k += 4) {
            float4 w  = *(const float4*)&wr[k];
            float4 x0 = *(const float4*)&h0[k];
            float4 x1 = *(const float4*)&h1[k];
            float4 x2 = *(const float4*)&h2[k];
            float4 x3 = *(const float4*)&h3[k];
            a0 = fmaf(w.x, x0.x, a0); a0 = fmaf(w.y, x0.y, a0); a0 = fmaf(w.z, x0.z, a0); a0 = fmaf(w.w, x0.w, a0);
            a1 = fmaf(w.x, x1.x, a1); a1 = fmaf(w.y, x1.y, a1); a1 = fmaf(w.z, x1.z, a1); a1 = fmaf(w.w, x1.w, a1);
            a2 = fmaf(w.x, x2.x, a2); a2 = fmaf(w.y, x2.y, a2); a2 = fmaf(w.z, x2.z, a2); a2 = fmaf(w.w, x2.w, a2);
            a3 = fmaf(w.x, x3.x, a3); a3 = fmaf(w.y, x3.y, a3); a3 = fmaf(w.z, x3.z, a3); a3 = fmaf(w.w, x3.w, a3);
        }
        *(float4*)&gsm[r * 68 + b0] = make_float4(a0, a1, a2, a3);
        __syncthreads();
        // ---- stage C: LSTM cell for (jj, b) ----
        float gi = fsig (gsm[(jj)      * 68 + b]);
        float gf = fsig (gsm[(4 + jj)  * 68 + b]);
        float gg = ftanh_(gsm[(8 + jj) * 68 + b]);
        float go = fsig (gsm[(12 + jj) * 68 + b]);
        cst = gf * cst + gi * gg;
        float hv = go * ftanh_(cst);
        vmax = fmaxf(vmax, hv);
        g_hbuf[step & 1][d][b][jglob] = hv;
        __threadfence();
        __syncthreads();
        if (tid == 0) {
            atomicAdd(&g_bar[d], 1u);
            unsigned target = 64u * (unsigned)(step + 1);
            while (ldacq(&g_bar[d]) < target) __nanosleep(64);
        }
        __syncthreads();
        if (step < 511) {
            const float4* src = (const float4*)&g_hbuf[step & 1][d][0][0];
            float4* dh = (float4*)hsm;
            for (int idx = tid; idx < 64 * 256 / 4; idx += 256) dh[idx] = __ldcg(&src[idx]);
        }
        __syncthreads();
    }
    g_vfeat[b][d * 256 + jglob] = vmax;
}

// ---------------- final: out[b] = sum_j v[b][j]*(Wu[j] + txt·Wtl[j] + btl[j]) + bu ----------------
__global__ void final_kernel(const float* __restrict__ txt,
                             const float* __restrict__ Wu, const float* __restrict__ bu,
                             const float* __restrict__ Wtl, const float* __restrict__ btl,
                             float* __restrict__ out)
{
    __shared__ float ts[DTXT];
    __shared__ float red[512];
    int b = blockIdx.x, j = threadIdx.x;
    for (int i = j; i < DTXT; i += 512) ts[i] = txt[b * DTXT + i];
    __syncthreads();
    float tl = btl[j];
    const float4* wr = (const float4*)(Wtl + (size_t)j * DTXT);
    const float4* tv = (const float4*)ts;
#pragma unroll 8
    for (int i = 0; i < DTXT / 4; i++) {
        float4 w = wr[i], t = tv[i];
        tl += w.x * t.x + w.y * t.y + w.z * t.z + w.w * t.w;
    }
    float v = g_vfeat[b][j];
    red[j] = v * (Wu[j] + tl);
    __syncthreads();
    for (int s_ = 256; s_ > 0; s_ >>= 1) {
        if (j < s_) red[j] += red[j + s_];
        __syncthreads();
    }
    if (j == 0) out[b] = red[0] + bu[0];
}

// ---------------- launch ----------------
extern "C" void kernel_launch(void* const* d_in, const int* in_sizes, int n_in,
                              void* d_out, int out_size)
{
    const float* x    = (const float*)d_in[0];
    const float* txt  = (const float*)d_in[1];
    const float* Wvp  = (const float*)d_in[2];
    const float* bvp  = (const float*)d_in[3];
    const float* Wg1  = (const float*)d_in[4];
    const float* bg1  = (const float*)d_in[5];
    const float* Wg2  = (const float*)d_in[6];
    const float* bg2  = (const float*)d_in[7];
    const float* Wihf = (const float*)d_in[8];
    const float* Whhf = (const float*)d_in[9];
    const float* bihf = (const float*)d_in[10];
    const float* bhhf = (const float*)d_in[11];
    const float* Wihb = (const float*)d_in[12];
    const float* Whhb = (const float*)d_in[13];
    const float* bihb = (const float*)d_in[14];
    const float* bhhb = (const float*)d_in[15];
    const float* Wu   = (const float*)d_in[16];
    const float* bu   = (const float*)d_in[17];
    const float* Wtl  = (const float*)d_in[18];
    const float* btl  = (const float*)d_in[19];
    float* out = (float*)d_out;

    cudaFuncSetAttribute(scan_kernel, cudaFuncAttributeMaxDynamicSharedMemorySize, SCAN_SMEM_BYTES);

    gate_kernel<<<Bb, 256>>>(txt, Wg1, bg1, Wg2, bg2);
    gemm1_kernel<<<dim3(M1 / 128, 2), 256>>>(x, Wvp, bvp);
    gemm2_kernel<<<dim3(M1 / 128, 16), 256>>>(Wihf, Wihb, bihf, bhhf, bihb, bhhb);
    init_kernel<<<1, 32>>>();
    scan_kernel<<<128, 256, SCAN_SMEM_BYTES>>>(Whhf, Whhb);
    final_kernel<<<Bb, 512>>>(txt, Wu, bu, Wtl, btl, out);
}

// round 3
// speedup vs baseline: 1.3203x; 1.3203x over previous
#include <cuda_runtime.h>
#include <cuda_bf16.h>
#include <cstdint>
#include <math.h>

#define Hh    256
#define Bb    64
#define Ss    512
#define DIN   2818
#define DTXT  512
#define M1    32768   // Bb*Ss
#define KP1   2880    // padded K for gemm1 weights
#define NC1   89      // ceil(2818/32)
#define NC2   8       // 256/32

// ---------------- scratch (device globals) ----------------
__device__ float          g_xg[2][4 * Hh][M1];          // [dir][gate][s*64+b]
__device__ float          g_xf[(size_t)M1 * Hh];        // x_feat [s*64+b][h] fp32
__device__ float          g_hbuf[2][2][Bb][Hh];
__device__ float          g_gate[Bb * Hh];
__device__ float          g_vfeat[Bb][2 * Hh];
__device__ unsigned       g_bar[2];
__device__ __nv_bfloat16  g_whi[(size_t)Hh * KP1];      // Wvp hi  [256][2880]
__device__ __nv_bfloat16  g_wlo[(size_t)Hh * KP1];      // Wvp lo
__device__ __nv_bfloat16  g_wih_hi[(size_t)2048 * Hh];  // Wih (f then b) hi [2048][256]
__device__ __nv_bfloat16  g_wih_lo[(size_t)2048 * Hh];

__device__ __forceinline__ float fsig(float x)  { return 1.f / (1.f + __expf(-x)); }
__device__ __forceinline__ float ftanh_(float x){ return 2.f / (1.f + __expf(-2.f * x)) - 1.f; }

__device__ __forceinline__ unsigned ldacq(const unsigned* p) {
    unsigned v;
    asm volatile("ld.global.acquire.gpu.u32 %0, [%1];" : "=r"(v) : "l"(p));
    return v;
}
__device__ __forceinline__ uint32_t smem_u32(const void* p) {
    uint32_t a;
    asm("{ .reg .u64 t; cvta.to.shared.u64 t, %1; cvt.u32.u64 %0, t; }" : "=r"(a) : "l"(p));
    return a;
}
__device__ __forceinline__ void ldm4(uint32_t* r, uint32_t addr) {
    asm volatile("ldmatrix.sync.aligned.m8n8.x4.shared.b16 {%0,%1,%2,%3}, [%4];"
                 : "=r"(r[0]), "=r"(r[1]), "=r"(r[2]), "=r"(r[3]) : "r"(addr));
}
#define MMA(c, a, b) \
    asm volatile("mma.sync.aligned.m16n8k16.row.col.f32.bf16.bf16.f32 " \
                 "{%0,%1,%2,%3}, {%4,%5,%6,%7}, {%8,%9}, {%0,%1,%2,%3};" \
                 : "+f"((c)[0]), "+f"((c)[1]), "+f"((c)[2]), "+f"((c)[3]) \
                 : "r"((a)[0]), "r"((a)[1]), "r"((a)[2]), "r"((a)[3]), \
                   "r"((b)[0]), "r"((b)[1]))

// ---------------- prep: split weights into bf16 hi/lo ----------------
__global__ void prep_w(const float* __restrict__ Wvp,
                       const float* __restrict__ Wihf, const float* __restrict__ Wihb)
{
    const int T1 = Hh * KP1;        // 737280
    const int T2 = 2048 * Hh;       // 524288
    for (int i = blockIdx.x * 256 + threadIdx.x; i < T1 + T2; i += gridDim.x * 256) {
        if (i < T1) {
            int r = i / KP1, c = i % KP1;
            float v = (c < DIN) ? Wvp[(size_t)r * DIN + c] : 0.f;
            __nv_bfloat16 h = __float2bfloat16(v);
            g_whi[i] = h;
            g_wlo[i] = __float2bfloat16(v - __bfloat162float(h));
        } else {
            int j = i - T1;
            int n = j >> 8, c = j & 255;
            int dir = n >> 10, gr = n & 1023;
            float v = dir ? Wihb[(size_t)gr * Hh + c] : Wihf[(size_t)gr * Hh + c];
            __nv_bfloat16 h = __float2bfloat16(v);
            g_wih_hi[j] = h;
            g_wih_lo[j] = __float2bfloat16(v - __bfloat162float(h));
        }
    }
}

// ---------------- text gate ----------------
__global__ void gate_kernel(const float* __restrict__ txt,
                            const float* __restrict__ Wg1, const float* __restrict__ bg1,
                            const float* __restrict__ Wg2, const float* __restrict__ bg2)
{
    __shared__ float ts[DTXT];
    __shared__ float hs[Hh];
    int b = blockIdx.x, tid = threadIdx.x;
    for (int i = tid; i < DTXT; i += 256) ts[i] = txt[b * DTXT + i];
    __syncthreads();
    float s = bg1[tid];
    const float4* wr = (const float4*)(Wg1 + (size_t)tid * DTXT);
    const float4* tv = (const float4*)ts;
#pragma unroll 8
    for (int i = 0; i < DTXT / 4; i++) {
        float4 w = wr[i], t = tv[i];
        s += w.x * t.x + w.y * t.y + w.z * t.z + w.w * t.w;
    }
    hs[tid] = fmaxf(s, 0.f);
    __syncthreads();
    float s2 = bg2[tid];
    const float4* wr2 = (const float4*)(Wg2 + (size_t)tid * Hh);
    const float4* hv  = (const float4*)hs;
#pragma unroll 8
    for (int i = 0; i < Hh / 4; i++) {
        float4 w = wr2[i], t = hv[i];
        s2 += w.x * t.x + w.y * t.y + w.z * t.z + w.w * t.w;
    }
    g_gate[b * Hh + tid] = fsig(s2);
}

// ======================= mma.sync split-bf16 GEMMs =======================
// CTA tile 128(M) x 128(N), K chunks of 32. 8 warps = 4(m) x 2(n): warp tile 32 x 64.
// SMEM rows padded to 40 bf16 (80B) -> ldmatrix conflict-free.
#define LDSTR 40

// ---------------- GEMM1: x_feat = (x · Wvp^T + b) * gate ----------------
__global__ __launch_bounds__(256, 1) void g1_mma(const float* __restrict__ x,
                                                 const float* __restrict__ bvp)
{
    __shared__ __nv_bfloat16 Ah[128 * LDSTR], Al[128 * LDSTR];
    __shared__ __nv_bfloat16 Bh[128 * LDSTR], Bl[128 * LDSTR];

    int tid = threadIdx.x, lane = tid & 31, wid = tid >> 5;
    int m0 = blockIdx.x * 128, n0 = blockIdx.y * 128;
    int wm = (wid & 3) * 32, wn = (wid >> 2) * 64;

    int rA = (lane & 7) + ((lane >> 3) & 1) * 8;
    int kA = ((lane >> 4) & 1) * 16;
    int rB = (lane & 7) + ((lane >> 4) & 1) * 8;
    int kB = ((lane >> 3) & 1) * 16;
    uint32_t aBH = smem_u32(Ah), aBL = smem_u32(Al);
    uint32_t bBH = smem_u32(Bh), bBL = smem_u32(Bl);

    float acc[2][8][4];
#pragma unroll
    for (int i = 0; i < 2; i++)
#pragma unroll
        for (int j = 0; j < 8; j++)
#pragma unroll
            for (int q = 0; q < 4; q++) acc[i][j][q] = 0.f;

    float2 aR[8];
    uint4 bRh[2], bRl[2];

    // prefetch chunk 0
#pragma unroll
    for (int i = 0; i < 8; i++) {
        int lin = tid + i * 256, row = lin >> 4, cp = lin & 15;
        int gk = cp * 2;
        float2 v = make_float2(0.f, 0.f);
        if (gk + 1 < DIN) v = *(const float2*)(x + (size_t)(m0 + row) * DIN + gk);
        aR[i] = v;
    }
#pragma unroll
    for (int i = 0; i < 2; i++) {
        int lin = tid + i * 256, row = lin >> 2, c8 = (lin & 3) * 8;
        size_t o = (size_t)(n0 + row) * KP1 + c8;
        bRh[i] = *(const uint4*)(g_whi + o);
        bRl[i] = *(const uint4*)(g_wlo + o);
    }

    for (int kc = 0; kc < NC1; kc++) {
        // store regs -> smem (convert A)
#pragma unroll
        for (int i = 0; i < 8; i++) {
            int lin = tid + i * 256, row = lin >> 4, cp = lin & 15;
            float2 v = aR[i];
            __nv_bfloat16 h0 = __float2bfloat16(v.x), h1 = __float2bfloat16(v.y);
            __nv_bfloat162 hh, ll;
            hh.x = h0; hh.y = h1;
            ll.x = __float2bfloat16(v.x - __bfloat162float(h0));
            ll.y = __float2bfloat16(v.y - __bfloat162float(h1));
            *(__nv_bfloat162*)(Ah + row * LDSTR + cp * 2) = hh;
            *(__nv_bfloat162*)(Al + row * LDSTR + cp * 2) = ll;
        }
#pragma unroll
        for (int i = 0; i < 2; i++) {
            int lin = tid + i * 256, row = lin >> 2, c8 = (lin & 3) * 8;
            *(uint4*)(Bh + row * LDSTR + c8) = bRh[i];
            *(uint4*)(Bl + row * LDSTR + c8) = bRl[i];
        }
        __syncthreads();
        // prefetch next chunk
        if (kc + 1 < NC1) {
            int kb = (kc + 1) * 32;
#pragma unroll
            for (int i = 0; i < 8; i++) {
                int lin = tid + i * 256, row = lin >> 4, cp = lin & 15;
                int gk = kb + cp * 2;
                float2 v = make_float2(0.f, 0.f);
                if (gk + 1 < DIN) v = *(const float2*)(x + (size_t)(m0 + row) * DIN + gk);
                else if (gk < DIN) v.x = x[(size_t)(m0 + row) * DIN + gk];
                aR[i] = v;
            }
#pragma unroll
            for (int i = 0; i < 2; i++) {
                int lin = tid + i * 256, row = lin >> 2, c8 = (lin & 3) * 8;
                size_t o = (size_t)(n0 + row) * KP1 + kb + c8;
                bRh[i] = *(const uint4*)(g_whi + o);
                bRl[i] = *(const uint4*)(g_wlo + o);
            }
        }
        // compute
#pragma unroll
        for (int s = 0; s < 2; s++) {
            uint32_t ah[2][4], al[2][4], bh[4][4], bl[4][4];
#pragma unroll
            for (int mt = 0; mt < 2; mt++) {
                uint32_t off = (uint32_t)(wm + mt * 16 + rA) * (LDSTR * 2) + s * 32 + kA;
                ldm4(ah[mt], aBH + off);
                ldm4(al[mt], aBL + off);
            }
#pragma unroll
            for (int p = 0; p < 4; p++) {
                uint32_t off = (uint32_t)(wn + p * 16 + rB) * (LDSTR * 2) + s * 32 + kB;
                ldm4(bh[p], bBH + off);
                ldm4(bl[p], bBL + off);
            }
#pragma unroll
            for (int mt = 0; mt < 2; mt++)
#pragma unroll
                for (int nt = 0; nt < 8; nt++) {
                    uint32_t* fh = &bh[nt >> 1][(nt & 1) * 2];
                    uint32_t* fl = &bl[nt >> 1][(nt & 1) * 2];
                    MMA(acc[mt][nt], ah[mt], fh);
                    MMA(acc[mt][nt], al[mt], fh);
                    MMA(acc[mt][nt], ah[mt], fl);
                }
        }
        __syncthreads();
    }

    // epilogue: (acc + bias) * gate -> g_xf[(s*64+b)][h]
    int r = lane >> 2, cp = (lane & 3) * 2;
#pragma unroll
    for (int mt = 0; mt < 2; mt++) {
#pragma unroll
        for (int half = 0; half < 2; half++) {
            int mrow = m0 + wm + mt * 16 + r + half * 8;
            int bat = mrow >> 9, sidx = mrow & 511;
            float* dst = g_xf + (size_t)(sidx * 64 + bat) * Hh;
#pragma unroll
            for (int nt = 0; nt < 8; nt++) {
                int n = n0 + wn + nt * 8 + cp;
                float2 o;
                o.x = (acc[mt][nt][half * 2 + 0] + bvp[n])     * g_gate[bat * Hh + n];
                o.y = (acc[mt][nt][half * 2 + 1] + bvp[n + 1]) * g_gate[bat * Hh + n + 1];
                *(float2*)(dst + n) = o;
            }
        }
    }
}

// ---------------- GEMM2: xg = x_feat · Wih^T + bias (transposed write) ----------------
__global__ __launch_bounds__(256, 1) void g2_mma(const float* __restrict__ bihf, const float* __restrict__ bhhf,
                                                 const float* __restrict__ bihb, const float* __restrict__ bhhb)
{
    __shared__ __nv_bfloat16 Ah[128 * LDSTR], Al[128 * LDSTR];
    __shared__ __nv_bfloat16 Bh[128 * LDSTR], Bl[128 * LDSTR];

    int tid = threadIdx.x, lane = tid & 31, wid = tid >> 5;
    int m0 = blockIdx.x * 128, n0 = blockIdx.y * 128;
    int wm = (wid & 3) * 32, wn = (wid >> 2) * 64;

    int rA = (lane & 7) + ((lane >> 3) & 1) * 8;
    int kA = ((lane >> 4) & 1) * 16;
    int rB = (lane & 7) + ((lane >> 4) & 1) * 8;
    int kB = ((lane >> 3) & 1) * 16;
    uint32_t aBH = smem_u32(Ah), aBL = smem_u32(Al);
    uint32_t bBH = smem_u32(Bh), bBL = smem_u32(Bl);

    float acc[2][8][4];
#pragma unroll
    for (int i = 0; i < 2; i++)
#pragma unroll
        for (int j = 0; j < 8; j++)
#pragma unroll
            for (int q = 0; q < 4; q++) acc[i][j][q] = 0.f;

    float2 aR[8];
    uint4 bRh[2], bRl[2];

#pragma unroll
    for (int i = 0; i < 8; i++) {
        int lin = tid + i * 256, row = lin >> 4, cp = lin & 15;
        aR[i] = *(const float2*)(g_xf + (size_t)(m0 + row) * Hh + cp * 2);
    }
#pragma unroll
    for (int i = 0; i < 2; i++) {
        int lin = tid + i * 256, row = lin >> 2, c8 = (lin & 3) * 8;
        size_t o = (size_t)(n0 + row) * Hh + c8;
        bRh[i] = *(const uint4*)(g_wih_hi + o);
        bRl[i] = *(const uint4*)(g_wih_lo + o);
    }

    for (int kc = 0; kc < NC2; kc++) {
#pragma unroll
        for (int i = 0; i < 8; i++) {
            int lin = tid + i * 256, row = lin >> 4, cp = lin & 15;
            float2 v = aR[i];
            __nv_bfloat16 h0 = __float2bfloat16(v.x), h1 = __float2bfloat16(v.y);
            __nv_bfloat162 hh, ll;
            hh.x = h0; hh.y = h1;
            ll.x = __float2bfloat16(v.x - __bfloat162float(h0));
            ll.y = __float2bfloat16(v.y - __bfloat162float(h1));
            *(__nv_bfloat162*)(Ah + row * LDSTR + cp * 2) = hh;
            *(__nv_bfloat162*)(Al + row * LDSTR + cp * 2) = ll;
        }
#pragma unroll
        for (int i = 0; i < 2; i++) {
            int lin = tid + i * 256, row = lin >> 2, c8 = (lin & 3) * 8;
            *(uint4*)(Bh + row * LDSTR + c8) = bRh[i];
            *(uint4*)(Bl + row * LDSTR + c8) = bRl[i];
        }
        __syncthreads();
        if (kc + 1 < NC2) {
            int kb = (kc + 1) * 32;
#pragma unroll
            for (int i = 0; i < 8; i++) {
                int lin = tid + i * 256, row = lin >> 4, cp = lin & 15;
                aR[i] = *(const float2*)(g_xf + (size_t)(m0 + row) * Hh + kb + cp * 2);
            }
#pragma unroll
            for (int i = 0; i < 2; i++) {
                int lin = tid + i * 256, row = lin >> 2, c8 = (lin & 3) * 8;
                size_t o = (size_t)(n0 + row) * Hh + kb + c8;
                bRh[i] = *(const uint4*)(g_wih_hi + o);
                bRl[i] = *(const uint4*)(g_wih_lo + o);
            }
        }
#pragma unroll
        for (int s = 0; s < 2; s++) {
            uint32_t ah[2][4], al[2][4], bh[4][4], bl[4][4];
#pragma unroll
            for (int mt = 0; mt < 2; mt++) {
                uint32_t off = (uint32_t)(wm + mt * 16 + rA) * (LDSTR * 2) + s * 32 + kA;
                ldm4(ah[mt], aBH + off);
                ldm4(al[mt], aBL + off);
            }
#pragma unroll
            for (int p = 0; p < 4; p++) {
                uint32_t off = (uint32_t)(wn + p * 16 + rB) * (LDSTR * 2) + s * 32 + kB;
                ldm4(bh[p], bBH + off);
                ldm4(bl[p], bBL + off);
            }
#pragma unroll
            for (int mt = 0; mt < 2; mt++)
#pragma unroll
                for (int nt = 0; nt < 8; nt++) {
                    uint32_t* fh = &bh[nt >> 1][(nt & 1) * 2];
                    uint32_t* fl = &bl[nt >> 1][(nt & 1) * 2];
                    MMA(acc[mt][nt], ah[mt], fh);
                    MMA(acc[mt][nt], al[mt], fh);
                    MMA(acc[mt][nt], ah[mt], fl);
                }
        }
        __syncthreads();
    }

    // epilogue: acc + (bih+bhh) -> g_xg[dir][gate_row][m']  (transposed)
    int r = lane >> 2, cp = (lane & 3) * 2;
#pragma unroll
    for (int mt = 0; mt < 2; mt++) {
#pragma unroll
        for (int half = 0; half < 2; half++) {
            int mrow = m0 + wm + mt * 16 + r + half * 8;
#pragma unroll
            for (int nt = 0; nt < 8; nt++) {
                int n = n0 + wn + nt * 8 + cp;
                int dir = n >> 10, gr = n & 1023;
                const float* bi = dir ? bihb : bihf;
                const float* bh_ = dir ? bhhb : bhhf;
                g_xg[dir][gr][mrow]     = acc[mt][nt][half * 2 + 0] + bi[gr] + bh_[gr];
                g_xg[dir][gr + 1][mrow] = acc[mt][nt][half * 2 + 1] + bi[gr + 1] + bh_[gr + 1];
            }
        }
    }
}

// ---------------- barrier init ----------------
__global__ void init_kernel() {
    if (threadIdx.x < 2) g_bar[threadIdx.x] = 0u;
}

// ---------------- persistent bidirectional LSTM scan (unchanged, proven) ----------------
#define SCAN_SMEM_BYTES ((64 * 256 + 16 * 260 + 16 * 68) * 4)

__global__ __launch_bounds__(256, 1) void scan_kernel(const float* __restrict__ Whhf,
                                                      const float* __restrict__ Whhb)
{
    extern __shared__ float sm[];
    float* hsm = sm;
    float* Wsm = sm + 64 * 256;
    float* gsm = Wsm + 16 * 260;

    int tid = threadIdx.x;
    int d = blockIdx.x >> 6;
    int c = blockIdx.x & 63;
    const float* Whh = d ? Whhb : Whhf;

    for (int idx = tid; idx < 16 * 256; idx += 256) {
        int r = idx >> 8, k = idx & 255;
        int q = r >> 2, j2 = r & 3;
        Wsm[r * 260 + k] = Whh[(size_t)(q * 256 + 4 * c + j2) * Hh + k];
    }
    for (int idx = tid; idx < 64 * 256; idx += 256) hsm[idx] = 0.f;

    int r  = tid & 15, bc = tid >> 4, b0 = bc << 2;
    int qr = r >> 2,  jr = r & 3;
    const float* xg_row = g_xg[d][qr * 256 + 4 * c + jr];
    const float* wr = &Wsm[r * 260];

    int jj = tid >> 6, b = tid & 63;
    int jglob = 4 * c + jj;
    float cst = 0.f, vmax = -3.4e38f;

    __syncthreads();

    for (int step = 0; step < 512; step++) {
        int t = d ? (511 - step) : step;
        float4 xa = *(const float4*)&xg_row[t * 64 + b0];
        float a0 = xa.x, a1 = xa.y, a2 = xa.z, a3 = xa.w;
        const float* h0 = &hsm[(size_t)b0 * 256];
        const float* h1 = h0 + 256;
        const float* h2 = h0 + 512;
        const float* h3 = h0 + 768;
#pragma unroll 8
        for (int k = 0; k < 256; k += 4) {
            float4 w  = *(const float4*)&wr[k];
            float4 x0 = *(const float4*)&h0[k];
            float4 x1 = *(const float4*)&h1[k];
            float4 x2 = *(const float4*)&h2[k];
            float4 x3 = *(const float4*)&h3[k];
            a0 = fmaf(w.x, x0.x, a0); a0 = fmaf(w.y, x0.y, a0); a0 = fmaf(w.z, x0.z, a0); a0 = fmaf(w.w, x0.w, a0);
            a1 = fmaf(w.x, x1.x, a1); a1 = fmaf(w.y, x1.y, a1); a1 = fmaf(w.z, x1.z, a1); a1 = fmaf(w.w, x1.w, a1);
            a2 = fmaf(w.x, x2.x, a2); a2 = fmaf(w.y, x2.y, a2); a2 = fmaf(w.z, x2.z, a2); a2 = fmaf(w.w, x2.w, a2);
            a3 = fmaf(w.x, x3.x, a3); a3 = fmaf(w.y, x3.y, a3); a3 = fmaf(w.z, x3.z, a3); a3 = fmaf(w.w, x3.w, a3);
        }
        *(float4*)&gsm[r * 68 + b0] = make_float4(a0, a1, a2, a3);
        __syncthreads();
        float gi = fsig (gsm[(jj)      * 68 + b]);
        float gf = fsig (gsm[(4 + jj)  * 68 + b]);
        float gg = ftanh_(gsm[(8 + jj) * 68 + b]);
        float go = fsig (gsm[(12 + jj) * 68 + b]);
        cst = gf * cst + gi * gg;
        float hv = go * ftanh_(cst);
        vmax = fmaxf(vmax, hv);
        g_hbuf[step & 1][d][b][jglob] = hv;
        __threadfence();
        __syncthreads();
        if (tid == 0) {
            atomicAdd(&g_bar[d], 1u);
            unsigned target = 64u * (unsigned)(step + 1);
            while (ldacq(&g_bar[d]) < target) __nanosleep(64);
        }
        __syncthreads();
        if (step < 511) {
            const float4* src = (const float4*)&g_hbuf[step & 1][d][0][0];
            float4* dh = (float4*)hsm;
            for (int idx = tid; idx < 64 * 256 / 4; idx += 256) dh[idx] = __ldcg(&src[idx]);
        }
        __syncthreads();
    }
    g_vfeat[b][d * 256 + jglob] = vmax;
}

// ---------------- final ----------------
__global__ void final_kernel(const float* __restrict__ txt,
                             const float* __restrict__ Wu, const float* __restrict__ bu,
                             const float* __restrict__ Wtl, const float* __restrict__ btl,
                             float* __restrict__ out)
{
    __shared__ float ts[DTXT];
    __shared__ float red[512];
    int b = blockIdx.x, j = threadIdx.x;
    for (int i = j; i < DTXT; i += 512) ts[i] = txt[b * DTXT + i];
    __syncthreads();
    float tl = btl[j];
    const float4* wr = (const float4*)(Wtl + (size_t)j * DTXT);
    const float4* tv = (const float4*)ts;
#pragma unroll 8
    for (int i = 0; i < DTXT / 4; i++) {
        float4 w = wr[i], t = tv[i];
        tl += w.x * t.x + w.y * t.y + w.z * t.z + w.w * t.w;
    }
    float v = g_vfeat[b][j];
    red[j] = v * (Wu[j] + tl);
    __syncthreads();
    for (int s_ = 256; s_ > 0; s_ >>= 1) {
        if (j < s_) red[j] += red[j + s_];
        __syncthreads();
    }
    if (j == 0) out[b] = red[0] + bu[0];
}

// ---------------- launch ----------------
extern "C" void kernel_launch(void* const* d_in, const int* in_sizes, int n_in,
                              void* d_out, int out_size)
{
    const float* x    = (const float*)d_in[0];
    const float* txt  = (const float*)d_in[1];
    const float* Wvp  = (const float*)d_in[2];
    const float* bvp  = (const float*)d_in[3];
    const float* Wg1  = (const float*)d_in[4];
    const float* bg1  = (const float*)d_in[5];
    const float* Wg2  = (const float*)d_in[6];
    const float* bg2  = (const float*)d_in[7];
    const float* Wihf = (const float*)d_in[8];
    const float* Whhf = (const float*)d_in[9];
    const float* bihf = (const float*)d_in[10];
    const float* bhhf = (const float*)d_in[11];
    const float* Wihb = (const float*)d_in[12];
    const float* Whhb = (const float*)d_in[13];
    const float* bihb = (const float*)d_in[14];
    const float* bhhb = (const float*)d_in[15];
    const float* Wu   = (const float*)d_in[16];
    const float* bu   = (const float*)d_in[17];
    const float* Wtl  = (const float*)d_in[18];
    const float* btl  = (const float*)d_in[19];
    float* out = (float*)d_out;

    cudaFuncSetAttribute(scan_kernel, cudaFuncAttributeMaxDynamicSharedMemorySize, SCAN_SMEM_BYTES);

    prep_w<<<512, 256>>>(Wvp, Wihf, Wihb);
    gate_kernel<<<Bb, 256>>>(txt, Wg1, bg1, Wg2, bg2);
    g1_mma<<<dim3(M1 / 128, 2), 256>>>(x, bvp);
    g2_mma<<<dim3(M1 / 128, 16), 256>>>(bihf, bhhf, bihb, bhhb);
    init_kernel<<<1, 32>>>();
    scan_kernel<<<128, 256, SCAN_SMEM_BYTES>>>(Whhf, Whhb);
    final_kernel<<<Bb, 512>>>(txt, Wu, bu, Wtl, btl, out);
}

// round 4
// speedup vs baseline: 1.4341x; 1.0862x over previous
#include <cuda_runtime.h>
#include <cuda_bf16.h>
#include <cstdint>
#include <math.h>

#define Hh    256
#define Bb    64
#define Ss    512
#define DIN   2818
#define DTXT  512
#define M1    32768   // Bb*Ss
#define KP1   2880    // padded K for gemm1 weights
#define NC1   89      // ceil(2818/32)
#define NC2   8       // 256/32

// ---------------- scratch (device globals) ----------------
__device__ float          g_xg[2][4 * Hh][M1];          // [dir][gate][s*64+b]
__device__ float          g_xf[(size_t)M1 * Hh];        // x_feat [s*64+b][h] fp32
__device__ float          g_gate[Bb * Hh];
__device__ float          g_vfeat[Bb][2 * Hh];
__device__ unsigned       g_bar[2];
__device__ uint32_t       g_hpub[2][Bb][Hh];            // packed (hi,lo) bf16 per (b,hd)
__device__ __nv_bfloat16  g_whi[(size_t)Hh * KP1];      // Wvp hi  [256][2880]
__device__ __nv_bfloat16  g_wlo[(size_t)Hh * KP1];      // Wvp lo
__device__ __nv_bfloat16  g_wih_hi[(size_t)2048 * Hh];  // Wih (f then b) hi [2048][256]
__device__ __nv_bfloat16  g_wih_lo[(size_t)2048 * Hh];
__device__ __nv_bfloat16  g_whh_hi[2][1024][Hh];        // Whh hi [dir][gate_row][k]
__device__ __nv_bfloat16  g_whh_lo[2][1024][Hh];

__device__ __forceinline__ float fsig(float x)  { return 1.f / (1.f + __expf(-x)); }
__device__ __forceinline__ float ftanh_(float x){ return 2.f / (1.f + __expf(-2.f * x)) - 1.f; }

__device__ __forceinline__ unsigned ldacq(const unsigned* p) {
    unsigned v;
    asm volatile("ld.global.acquire.gpu.u32 %0, [%1];" : "=r"(v) : "l"(p));
    return v;
}
__device__ __forceinline__ uint32_t smem_u32(const void* p) {
    uint32_t a;
    asm("{ .reg .u64 t; cvta.to.shared.u64 t, %1; cvt.u32.u64 %0, t; }" : "=r"(a) : "l"(p));
    return a;
}
__device__ __forceinline__ void ldm4(uint32_t* r, uint32_t addr) {
    asm volatile("ldmatrix.sync.aligned.m8n8.x4.shared.b16 {%0,%1,%2,%3}, [%4];"
                 : "=r"(r[0]), "=r"(r[1]), "=r"(r[2]), "=r"(r[3]) : "r"(addr));
}
#define MMA(c, a, b) \
    asm volatile("mma.sync.aligned.m16n8k16.row.col.f32.bf16.bf16.f32 " \
                 "{%0,%1,%2,%3}, {%4,%5,%6,%7}, {%8,%9}, {%0,%1,%2,%3};" \
                 : "+f"((c)[0]), "+f"((c)[1]), "+f"((c)[2]), "+f"((c)[3]) \
                 : "r"((a)[0]), "r"((a)[1]), "r"((a)[2]), "r"((a)[3]), \
                   "r"((b)[0]), "r"((b)[1]))

// ---------------- prep: split weights into bf16 hi/lo ----------------
__global__ void prep_w(const float* __restrict__ Wvp,
                       const float* __restrict__ Wihf, const float* __restrict__ Wihb,
                       const float* __restrict__ Whhf, const float* __restrict__ Whhb)
{
    const int T1 = Hh * KP1;        // 737280
    const int T2 = 2048 * Hh;       // 524288
    const int T3 = 2 * 1024 * Hh;   // 524288
    for (int i = blockIdx.x * 256 + threadIdx.x; i < T1 + T2 + T3; i += gridDim.x * 256) {
        if (i < T1) {
            int r = i / KP1, c = i % KP1;
            float v = (c < DIN) ? Wvp[(size_t)r * DIN + c] : 0.f;
            __nv_bfloat16 h = __float2bfloat16(v);
            g_whi[i] = h;
            g_wlo[i] = __float2bfloat16(v - __bfloat162float(h));
        } else if (i < T1 + T2) {
            int j = i - T1;
            int n = j >> 8, c = j & 255;
            int dir = n >> 10, gr = n & 1023;
            float v = dir ? Wihb[(size_t)gr * Hh + c] : Wihf[(size_t)gr * Hh + c];
            __nv_bfloat16 h = __float2bfloat16(v);
            g_wih_hi[j] = h;
            g_wih_lo[j] = __float2bfloat16(v - __bfloat162float(h));
        } else {
            int j = i - T1 - T2;
            int dir = j >> 18;
            int r = (j >> 8) & 1023, c = j & 255;
            float v = dir ? Whhb[(size_t)r * Hh + c] : Whhf[(size_t)r * Hh + c];
            __nv_bfloat16 h = __float2bfloat16(v);
            g_whh_hi[dir][r][c] = h;
            g_whh_lo[dir][r][c] = __float2bfloat16(v - __bfloat162float(h));
        }
    }
}

// ---------------- text gate ----------------
__global__ void gate_kernel(const float* __restrict__ txt,
                            const float* __restrict__ Wg1, const float* __restrict__ bg1,
                            const float* __restrict__ Wg2, const float* __restrict__ bg2)
{
    __shared__ float ts[DTXT];
    __shared__ float hs[Hh];
    int b = blockIdx.x, tid = threadIdx.x;
    for (int i = tid; i < DTXT; i += 256) ts[i] = txt[b * DTXT + i];
    __syncthreads();
    float s = bg1[tid];
    const float4* wr = (const float4*)(Wg1 + (size_t)tid * DTXT);
    const float4* tv = (const float4*)ts;
#pragma unroll 8
    for (int i = 0; i < DTXT / 4; i++) {
        float4 w = wr[i], t = tv[i];
        s += w.x * t.x + w.y * t.y + w.z * t.z + w.w * t.w;
    }
    hs[tid] = fmaxf(s, 0.f);
    __syncthreads();
    float s2 = bg2[tid];
    const float4* wr2 = (const float4*)(Wg2 + (size_t)tid * Hh);
    const float4* hv  = (const float4*)hs;
#pragma unroll 8
    for (int i = 0; i < Hh / 4; i++) {
        float4 w = wr2[i], t = hv[i];
        s2 += w.x * t.x + w.y * t.y + w.z * t.z + w.w * t.w;
    }
    g_gate[b * Hh + tid] = fsig(s2);
}

// ======================= mma.sync split-bf16 GEMMs =======================
#define LDSTR 40

// ---------------- GEMM1: x_feat = (x · Wvp^T + b) * gate ----------------
__global__ __launch_bounds__(256, 1) void g1_mma(const float* __restrict__ x,
                                                 const float* __restrict__ bvp)
{
    __shared__ __nv_bfloat16 Ah[128 * LDSTR], Al[128 * LDSTR];
    __shared__ __nv_bfloat16 Bh[128 * LDSTR], Bl[128 * LDSTR];

    int tid = threadIdx.x, lane = tid & 31, wid = tid >> 5;
    int m0 = blockIdx.x * 128, n0 = blockIdx.y * 128;
    int wm = (wid & 3) * 32, wn = (wid >> 2) * 64;

    int rA = (lane & 7) + ((lane >> 3) & 1) * 8;
    int kA = ((lane >> 4) & 1) * 16;
    int rB = (lane & 7) + ((lane >> 4) & 1) * 8;
    int kB = ((lane >> 3) & 1) * 16;
    uint32_t aBH = smem_u32(Ah), aBL = smem_u32(Al);
    uint32_t bBH = smem_u32(Bh), bBL = smem_u32(Bl);

    float acc[2][8][4];
#pragma unroll
    for (int i = 0; i < 2; i++)
#pragma unroll
        for (int j = 0; j < 8; j++)
#pragma unroll
            for (int q = 0; q < 4; q++) acc[i][j][q] = 0.f;

    float2 aR[8];
    uint4 bRh[2], bRl[2];

#pragma unroll
    for (int i = 0; i < 8; i++) {
        int lin = tid + i * 256, row = lin >> 4, cp = lin & 15;
        int gk = cp * 2;
        float2 v = make_float2(0.f, 0.f);
        if (gk + 1 < DIN) v = *(const float2*)(x + (size_t)(m0 + row) * DIN + gk);
        aR[i] = v;
    }
#pragma unroll
    for (int i = 0; i < 2; i++) {
        int lin = tid + i * 256, row = lin >> 2, c8 = (lin & 3) * 8;
        size_t o = (size_t)(n0 + row) * KP1 + c8;
        bRh[i] = *(const uint4*)(g_whi + o);
        bRl[i] = *(const uint4*)(g_wlo + o);
    }

    for (int kc = 0; kc < NC1; kc++) {
#pragma unroll
        for (int i = 0; i < 8; i++) {
            int lin = tid + i * 256, row = lin >> 4, cp = lin & 15;
            float2 v = aR[i];
            __nv_bfloat16 h0 = __float2bfloat16(v.x), h1 = __float2bfloat16(v.y);
            __nv_bfloat162 hh, ll;
            hh.x = h0; hh.y = h1;
            ll.x = __float2bfloat16(v.x - __bfloat162float(h0));
            ll.y = __float2bfloat16(v.y - __bfloat162float(h1));
            *(__nv_bfloat162*)(Ah + row * LDSTR + cp * 2) = hh;
            *(__nv_bfloat162*)(Al + row * LDSTR + cp * 2) = ll;
        }
#pragma unroll
        for (int i = 0; i < 2; i++) {
            int lin = tid + i * 256, row = lin >> 2, c8 = (lin & 3) * 8;
            *(uint4*)(Bh + row * LDSTR + c8) = bRh[i];
            *(uint4*)(Bl + row * LDSTR + c8) = bRl[i];
        }
        __syncthreads();
        if (kc + 1 < NC1) {
            int kb = (kc + 1) * 32;
#pragma unroll
            for (int i = 0; i < 8; i++) {
                int lin = tid + i * 256, row = lin >> 4, cp = lin & 15;
                int gk = kb + cp * 2;
                float2 v = make_float2(0.f, 0.f);
                if (gk + 1 < DIN) v = *(const float2*)(x + (size_t)(m0 + row) * DIN + gk);
                else if (gk < DIN) v.x = x[(size_t)(m0 + row) * DIN + gk];
                aR[i] = v;
            }
#pragma unroll
            for (int i = 0; i < 2; i++) {
                int lin = tid + i * 256, row = lin >> 2, c8 = (lin & 3) * 8;
                size_t o = (size_t)(n0 + row) * KP1 + kb + c8;
                bRh[i] = *(const uint4*)(g_whi + o);
                bRl[i] = *(const uint4*)(g_wlo + o);
            }
        }
#pragma unroll
        for (int s = 0; s < 2; s++) {
            uint32_t ah[2][4], al[2][4], bh[4][4], bl[4][4];
#pragma unroll
            for (int mt = 0; mt < 2; mt++) {
                uint32_t off = (uint32_t)(wm + mt * 16 + rA) * (LDSTR * 2) + s * 32 + kA;
                ldm4(ah[mt], aBH + off);
                ldm4(al[mt], aBL + off);
            }
#pragma unroll
            for (int p = 0; p < 4; p++) {
                uint32_t off = (uint32_t)(wn + p * 16 + rB) * (LDSTR * 2) + s * 32 + kB;
                ldm4(bh[p], bBH + off);
                ldm4(bl[p], bBL + off);
            }
#pragma unroll
            for (int mt = 0; mt < 2; mt++)
#pragma unroll
                for (int nt = 0; nt < 8; nt++) {
                    uint32_t* fh = &bh[nt >> 1][(nt & 1) * 2];
                    uint32_t* fl = &bl[nt >> 1][(nt & 1) * 2];
                    MMA(acc[mt][nt], ah[mt], fh);
                    MMA(acc[mt][nt], al[mt], fh);
                    MMA(acc[mt][nt], ah[mt], fl);
                }
        }
        __syncthreads();
    }

    int r = lane >> 2, cp = (lane & 3) * 2;
#pragma unroll
    for (int mt = 0; mt < 2; mt++) {
#pragma unroll
        for (int half = 0; half < 2; half++) {
            int mrow = m0 + wm + mt * 16 + r + half * 8;
            int bat = mrow >> 9, sidx = mrow & 511;
            float* dst = g_xf + (size_t)(sidx * 64 + bat) * Hh;
#pragma unroll
            for (int nt = 0; nt < 8; nt++) {
                int n = n0 + wn + nt * 8 + cp;
                float2 o;
                o.x = (acc[mt][nt][half * 2 + 0] + bvp[n])     * g_gate[bat * Hh + n];
                o.y = (acc[mt][nt][half * 2 + 1] + bvp[n + 1]) * g_gate[bat * Hh + n + 1];
                *(float2*)(dst + n) = o;
            }
        }
    }
}

// ---------------- GEMM2: xg = x_feat · Wih^T + bias (transposed write) ----------------
__global__ __launch_bounds__(256, 1) void g2_mma(const float* __restrict__ bihf, const float* __restrict__ bhhf,
                                                 const float* __restrict__ bihb, const float* __restrict__ bhhb)
{
    __shared__ __nv_bfloat16 Ah[128 * LDSTR], Al[128 * LDSTR];
    __shared__ __nv_bfloat16 Bh[128 * LDSTR], Bl[128 * LDSTR];

    int tid = threadIdx.x, lane = tid & 31, wid = tid >> 5;
    int m0 = blockIdx.x * 128, n0 = blockIdx.y * 128;
    int wm = (wid & 3) * 32, wn = (wid >> 2) * 64;

    int rA = (lane & 7) + ((lane >> 3) & 1) * 8;
    int kA = ((lane >> 4) & 1) * 16;
    int rB = (lane & 7) + ((lane >> 4) & 1) * 8;
    int kB = ((lane >> 3) & 1) * 16;
    uint32_t aBH = smem_u32(Ah), aBL = smem_u32(Al);
    uint32_t bBH = smem_u32(Bh), bBL = smem_u32(Bl);

    float acc[2][8][4];
#pragma unroll
    for (int i = 0; i < 2; i++)
#pragma unroll
        for (int j = 0; j < 8; j++)
#pragma unroll
            for (int q = 0; q < 4; q++) acc[i][j][q] = 0.f;

    float2 aR[8];
    uint4 bRh[2], bRl[2];

#pragma unroll
    for (int i = 0; i < 8; i++) {
        int lin = tid + i * 256, row = lin >> 4, cp = lin & 15;
        aR[i] = *(const float2*)(g_xf + (size_t)(m0 + row) * Hh + cp * 2);
    }
#pragma unroll
    for (int i = 0; i < 2; i++) {
        int lin = tid + i * 256, row = lin >> 2, c8 = (lin & 3) * 8;
        size_t o = (size_t)(n0 + row) * Hh + c8;
        bRh[i] = *(const uint4*)(g_wih_hi + o);
        bRl[i] = *(const uint4*)(g_wih_lo + o);
    }

    for (int kc = 0; kc < NC2; kc++) {
#pragma unroll
        for (int i = 0; i < 8; i++) {
            int lin = tid + i * 256, row = lin >> 4, cp = lin & 15;
            float2 v = aR[i];
            __nv_bfloat16 h0 = __float2bfloat16(v.x), h1 = __float2bfloat16(v.y);
            __nv_bfloat162 hh, ll;
            hh.x = h0; hh.y = h1;
            ll.x = __float2bfloat16(v.x - __bfloat162float(h0));
            ll.y = __float2bfloat16(v.y - __bfloat162float(h1));
            *(__nv_bfloat162*)(Ah + row * LDSTR + cp * 2) = hh;
            *(__nv_bfloat162*)(Al + row * LDSTR + cp * 2) = ll;
        }
#pragma unroll
        for (int i = 0; i < 2; i++) {
            int lin = tid + i * 256, row = lin >> 2, c8 = (lin & 3) * 8;
            *(uint4*)(Bh + row * LDSTR + c8) = bRh[i];
            *(uint4*)(Bl + row * LDSTR + c8) = bRl[i];
        }
        __syncthreads();
        if (kc + 1 < NC2) {
            int kb = (kc + 1) * 32;
#pragma unroll
            for (int i = 0; i < 8; i++) {
                int lin = tid + i * 256, row = lin >> 4, cp = lin & 15;
                aR[i] = *(const float2*)(g_xf + (size_t)(m0 + row) * Hh + kb + cp * 2);
            }
#pragma unroll
            for (int i = 0; i < 2; i++) {
                int lin = tid + i * 256, row = lin >> 2, c8 = (lin & 3) * 8;
                size_t o = (size_t)(n0 + row) * Hh + kb + c8;
                bRh[i] = *(const uint4*)(g_wih_hi + o);
                bRl[i] = *(const uint4*)(g_wih_lo + o);
            }
        }
#pragma unroll
        for (int s = 0; s < 2; s++) {
            uint32_t ah[2][4], al[2][4], bh[4][4], bl[4][4];
#pragma unroll
            for (int mt = 0; mt < 2; mt++) {
                uint32_t off = (uint32_t)(wm + mt * 16 + rA) * (LDSTR * 2) + s * 32 + kA;
                ldm4(ah[mt], aBH + off);
                ldm4(al[mt], aBL + off);
            }
#pragma unroll
            for (int p = 0; p < 4; p++) {
                uint32_t off = (uint32_t)(wn + p * 16 + rB) * (LDSTR * 2) + s * 32 + kB;
                ldm4(bh[p], bBH + off);
                ldm4(bl[p], bBL + off);
            }
#pragma unroll
            for (int mt = 0; mt < 2; mt++)
#pragma unroll
                for (int nt = 0; nt < 8; nt++) {
                    uint32_t* fh = &bh[nt >> 1][(nt & 1) * 2];
                    uint32_t* fl = &bl[nt >> 1][(nt & 1) * 2];
                    MMA(acc[mt][nt], ah[mt], fh);
                    MMA(acc[mt][nt], al[mt], fh);
                    MMA(acc[mt][nt], ah[mt], fl);
                }
        }
        __syncthreads();
    }

    int r = lane >> 2, cp = (lane & 3) * 2;
#pragma unroll
    for (int mt = 0; mt < 2; mt++) {
#pragma unroll
        for (int half = 0; half < 2; half++) {
            int mrow = m0 + wm + mt * 16 + r + half * 8;
#pragma unroll
            for (int nt = 0; nt < 8; nt++) {
                int n = n0 + wn + nt * 8 + cp;
                int dir = n >> 10, gr = n & 1023;
                const float* bi = dir ? bihb : bihf;
                const float* bh_ = dir ? bhhb : bhhf;
                g_xg[dir][gr][mrow]     = acc[mt][nt][half * 2 + 0] + bi[gr] + bh_[gr];
                g_xg[dir][gr + 1][mrow] = acc[mt][nt][half * 2 + 1] + bi[gr + 1] + bh_[gr + 1];
            }
        }
    }
}

// ---------------- barrier init ----------------
__global__ void init_kernel() {
    if (threadIdx.x < 2) g_bar[threadIdx.x] = 0u;
}

// =============== tensor-core persistent bidirectional LSTM scan ===============
// 128 CTAs: dir = blockIdx.x>>6, cblk = blockIdx.x&63 owns h-dims [4c,4c+4).
// Per step: G^T[16 gates x 64 batches] = Whh_slice(bf16 hi/lo, reg-resident A frags)
//           x h(bf16 hi/lo in SMEM, ldmatrix B frags), C init = xg (prefetched).
// 8 warps each own 8 batches. Stage C pairs (i,g)<->(f,o) rows via shfl.xor 16.
// h broadcast through L2 as packed (hi,lo) u32, per-direction global barrier.
#define HROW 264                       // bf16 row stride (528B): conflict-free ldmatrix
#define SCAN2_SMEM (2 * 64 * HROW * 2) // hi + lo = 67584 bytes

__global__ __launch_bounds__(256, 1) void scan_mma()
{
    extern __shared__ __nv_bfloat16 hs2[];
    __nv_bfloat16* hBhi = hs2;
    __nv_bfloat16* hBlo = hs2 + 64 * HROW;

    int tid = threadIdx.x, lane = tid & 31, wid = tid >> 5;
    int d = blockIdx.x >> 6, cblk = blockIdx.x & 63;
    int wb0 = wid * 8;

    // ---- A fragments (Whh slice) resident in registers ----
    uint32_t rah[16][4], ral[16][4];
    int r0 = lane >> 2, cq = (lane & 3) * 2;
    int row0 = (r0 >> 2) * 256 + 4 * cblk + (r0 & 3);        // m-rows 0-7: i(hd0-3), f(hd0-3)
    int row1 = ((r0 + 8) >> 2) * 256 + 4 * cblk + (r0 & 3);  // m-rows 8-15: g, o
    {
        const uint32_t* whi = (const uint32_t*)&g_whh_hi[d][0][0];
        const uint32_t* wlo = (const uint32_t*)&g_whh_lo[d][0][0];
#pragma unroll
        for (int kc = 0; kc < 16; kc++) {
            int cA = kc * 16 + cq;
            rah[kc][0] = whi[(row0 * 256 + cA) >> 1];
            rah[kc][1] = whi[(row1 * 256 + cA) >> 1];
            rah[kc][2] = whi[(row0 * 256 + cA + 8) >> 1];
            rah[kc][3] = whi[(row1 * 256 + cA + 8) >> 1];
            ral[kc][0] = wlo[(row0 * 256 + cA) >> 1];
            ral[kc][1] = wlo[(row1 * 256 + cA) >> 1];
            ral[kc][2] = wlo[(row0 * 256 + cA + 8) >> 1];
            ral[kc][3] = wlo[(row1 * 256 + cA + 8) >> 1];
        }
    }

    // zero h SMEM (h_0 = 0)
    {
        uint32_t* z = (uint32_t*)hs2;
        for (int i = tid; i < 64 * HROW; i += 256) z[i] = 0u;
    }

    // xg row pointers (rows match C fragment rows)
    const float* xgp0 = &g_xg[d][row0][0];
    const float* xgp1 = &g_xg[d][row1][0];
    int bcol = wb0 + 2 * (lane & 3);

    uint32_t bhiS = smem_u32(hBhi), bloS = smem_u32(hBlo);
    uint32_t rowbyte = (uint32_t)(wb0 + (lane & 7)) * (HROW * 2) + ((lane >> 3) & 3) * 16;

    // staging identity: thread -> (b = tid>>2, 64 cols at (tid&3)*64)
    int sb = tid >> 2, sc = (tid & 3) * 64;
    const uint4* pubsrc = (const uint4*)&g_hpub[d][sb][sc];
    uint32_t stHi = bhiS + (uint32_t)(sb * HROW + sc) * 2;
    uint32_t stLo = bloS + (uint32_t)(sb * HROW + sc) * 2;

    float cst0 = 0.f, cst1 = 0.f, vm0 = -3.4e38f, vm1 = -3.4e38f;
    int t0 = d ? 511 : 0;
    float2 nxa = *(const float2*)(xgp0 + t0 * 64 + bcol);
    float2 nxb = *(const float2*)(xgp1 + t0 * 64 + bcol);

    __syncthreads();

    for (int step = 0; step < 512; step++) {
        // ---- MMA: C = xg + Whh·h ----
        float c0[4] = {nxa.x, nxa.y, nxb.x, nxb.y};
        float c1[4] = {0.f, 0.f, 0.f, 0.f};
#pragma unroll
        for (int kc2 = 0; kc2 < 8; kc2++) {
            uint32_t bh4[4], bl4[4];
            uint32_t off = (uint32_t)(kc2 * 64) + rowbyte;
            ldm4(bh4, bhiS + off);
            ldm4(bl4, bloS + off);
            MMA(c0, rah[2 * kc2],     &bh4[0]);
            MMA(c1, rah[2 * kc2 + 1], &bh4[2]);
            MMA(c0, rah[2 * kc2],     &bl4[0]);
            MMA(c1, rah[2 * kc2 + 1], &bl4[2]);
            MMA(c0, ral[2 * kc2],     &bh4[0]);
            MMA(c1, ral[2 * kc2 + 1], &bh4[2]);
        }
        float g0v = c0[0] + c1[0], g1v = c0[1] + c1[1];
        float g2v = c0[2] + c1[2], g3v = c0[3] + c1[3];

        // ---- pair exchange: lanes<16 own (i,g), lanes>=16 own (f,o) ----
        float p0 = __shfl_xor_sync(0xffffffffu, g0v, 16);
        float p1 = __shfl_xor_sync(0xffffffffu, g1v, 16);
        float p2 = __shfl_xor_sync(0xffffffffu, g2v, 16);
        float p3 = __shfl_xor_sync(0xffffffffu, g3v, 16);
        bool hihalf = lane >= 16;
        float ia0 = hihalf ? p0 : g0v, ia1 = hihalf ? p1 : g1v;
        float ga0 = hihalf ? p2 : g2v, ga1 = hihalf ? p3 : g3v;
        float fa0 = hihalf ? g0v : p0, fa1 = hihalf ? g1v : p1;
        float oa0 = hihalf ? g2v : p2, oa1 = hihalf ? g3v : p3;

        cst0 = fsig(fa0) * cst0 + fsig(ia0) * ftanh_(ga0);
        cst1 = fsig(fa1) * cst1 + fsig(ia1) * ftanh_(ga1);
        float h0v = fsig(oa0) * ftanh_(cst0);
        float h1v = fsig(oa1) * ftanh_(cst1);
        vm0 = fmaxf(vm0, h0v);
        vm1 = fmaxf(vm1, h1v);

        if (!hihalf) {
            int hd = 4 * cblk + (lane >> 2);
            __nv_bfloat162 q0, q1;
            q0.x = __float2bfloat16(h0v);
            q0.y = __float2bfloat16(h0v - __bfloat162float(q0.x));
            q1.x = __float2bfloat16(h1v);
            q1.y = __float2bfloat16(h1v - __bfloat162float(q1.x));
            g_hpub[d][bcol][hd]     = *(uint32_t*)&q0;
            g_hpub[d][bcol + 1][hd] = *(uint32_t*)&q1;
        }
        // prefetch next xg while waiting
        if (step < 511) {
            int tn = d ? (510 - step) : (step + 1);
            nxa = *(const float2*)(xgp0 + tn * 64 + bcol);
            nxb = *(const float2*)(xgp1 + tn * 64 + bcol);
        }
        __threadfence();
        __syncthreads();
        if (tid == 0) {
            atomicAdd(&g_bar[d], 1u);
            unsigned target = 64u * (unsigned)(step + 1);
            while (ldacq(&g_bar[d]) < target) __nanosleep(64);
        }
        __syncthreads();
        // ---- reload h into SMEM (split hi/lo) ----
        if (step < 511) {
#pragma unroll
            for (int q = 0; q < 16; q++) {
                uint4 p = __ldcg(pubsrc + q);
                uint32_t h01 = (p.x & 0xFFFFu) | (p.y << 16);
                uint32_t h23 = (p.z & 0xFFFFu) | (p.w << 16);
                uint32_t l01 = (p.x >> 16) | (p.y & 0xFFFF0000u);
                uint32_t l23 = (p.z >> 16) | (p.w & 0xFFFF0000u);
                uint32_t boff = (uint32_t)q * 8;
                asm volatile("st.shared.v2.b32 [%0], {%1, %2};" :: "r"(stHi + boff), "r"(h01), "r"(h23));
                asm volatile("st.shared.v2.b32 [%0], {%1, %2};" :: "r"(stLo + boff), "r"(l01), "r"(l23));
            }
        }
        __syncthreads();
    }

    if (lane < 16) {
        int hd = 4 * cblk + (lane >> 2);
        g_vfeat[bcol][d * 256 + hd]     = vm0;
        g_vfeat[bcol + 1][d * 256 + hd] = vm1;
    }
}

// ---------------- final ----------------
__global__ void final_kernel(const float* __restrict__ txt,
                             const float* __restrict__ Wu, const float* __restrict__ bu,
                             const float* __restrict__ Wtl, const float* __restrict__ btl,
                             float* __restrict__ out)
{
    __shared__ float ts[DTXT];
    __shared__ float red[512];
    int b = blockIdx.x, j = threadIdx.x;
    for (int i = j; i < DTXT; i += 512) ts[i] = txt[b * DTXT + i];
    __syncthreads();
    float tl = btl[j];
    const float4* wr = (const float4*)(Wtl + (size_t)j * DTXT);
    const float4* tv = (const float4*)ts;
#pragma unroll 8
    for (int i = 0; i < DTXT / 4; i++) {
        float4 w = wr[i], t = tv[i];
        tl += w.x * t.x + w.y * t.y + w.z * t.z + w.w * t.w;
    }
    float v = g_vfeat[b][j];
    red[j] = v * (Wu[j] + tl);
    __syncthreads();
    for (int s_ = 256; s_ > 0; s_ >>= 1) {
        if (j < s_) red[j] += red[j + s_];
        __syncthreads();
    }
    if (j == 0) out[b] = red[0] + bu[0];
}

// ---------------- launch ----------------
extern "C" void kernel_launch(void* const* d_in, const int* in_sizes, int n_in,
                              void* d_out, int out_size)
{
    const float* x    = (const float*)d_in[0];
    const float* txt  = (const float*)d_in[1];
    const float* Wvp  = (const float*)d_in[2];
    const float* bvp  = (const float*)d_in[3];
    const float* Wg1  = (const float*)d_in[4];
    const float* bg1  = (const float*)d_in[5];
    const float* Wg2  = (const float*)d_in[6];
    const float* bg2  = (const float*)d_in[7];
    const float* Wihf = (const float*)d_in[8];
    const float* Whhf = (const float*)d_in[9];
    const float* bihf = (const float*)d_in[10];
    const float* bhhf = (const float*)d_in[11];
    const float* Wihb = (const float*)d_in[12];
    const float* Whhb = (const float*)d_in[13];
    const float* bihb = (const float*)d_in[14];
    const float* bhhb = (const float*)d_in[15];
    const float* Wu   = (const float*)d_in[16];
    const float* bu   = (const float*)d_in[17];
    const float* Wtl  = (const float*)d_in[18];
    const float* btl  = (const float*)d_in[19];
    float* out = (float*)d_out;

    cudaFuncSetAttribute(scan_mma, cudaFuncAttributeMaxDynamicSharedMemorySize, SCAN2_SMEM);

    prep_w<<<512, 256>>>(Wvp, Wihf, Wihb, Whhf, Whhb);
    gate_kernel<<<Bb, 256>>>(txt, Wg1, bg1, Wg2, bg2);
    g1_mma<<<dim3(M1 / 128, 2), 256>>>(x, bvp);
    g2_mma<<<dim3(M1 / 128, 16), 256>>>(bihf, bhhf, bihb, bhhb);
    init_kernel<<<1, 32>>>();
    scan_mma<<<128, 256, SCAN2_SMEM>>>();
    final_kernel<<<Bb, 512>>>(txt, Wu, bu, Wtl, btl, out);
}